// round 17
// baseline (speedup 1.0000x reference)
#include <cuda_runtime.h>

typedef unsigned long long ull;

// Problem constants
#define LSEQ 512
#define NH 12
#define FD 16
#define HD 64
#define DM 768
#define DREAL 273
#define DP 288
#define CH 8
#define CT 64
#define PROJ_N 1152
#define EPSV 1e-12f
#define PHI_S 0.17677669529663687f

#define GRID_P 148
#define NTHR 288
#define NSLANE (NH * DP * HD)
#define NZLANE (NH * DP)

// Scratch (device globals; no allocation allowed)
__device__ float g_P[LSEQ * PROJ_N];
__device__ float g_phiQ[NH * LSEQ * DP];
__device__ float g_phiK[NH * LSEQ * DP];
__device__ float g_S[NH * CH * DP * HD];
__device__ float g_Z[NH * CH * DP];
__device__ float g_Y[LSEQ * DM];

// Global barrier state
__device__ int g_bar_count;
__device__ int g_bar_sense;

// ---------------------------------------------------------------------------
// Packed f32x2 helpers
// ---------------------------------------------------------------------------
__device__ __forceinline__ ull dup2(float a) {
    ull r; asm("mov.b64 %0, {%1, %1};" : "=l"(r) : "f"(a)); return r;
}
__device__ __forceinline__ void fma2(ull& d, ull a, ull b) {
    asm("fma.rn.f32x2 %0, %1, %2, %0;" : "+l"(d) : "l"(a), "l"(b));
}
__device__ __forceinline__ float2 unpk(ull v) {
    float2 r; asm("mov.b64 {%0, %1}, %2;" : "=f"(r.x), "=f"(r.y) : "l"(v)); return r;
}

// ---------------------------------------------------------------------------
// Software grid barrier (sense-reversing). All 148 blocks co-resident.
// __threadfence() on both sides: release writes + L1 invalidate (CCTL.IVALL).
// ---------------------------------------------------------------------------
__device__ __forceinline__ void grid_sync(int* sense_sh) {
    __syncthreads();
    if (threadIdx.x == 0) {
        __threadfence();
        const int s = *sense_sh ^ 1;
        *sense_sh = s;
        if (atomicAdd(&g_bar_count, 1) == GRID_P - 1) {
            g_bar_count = 0;
            __threadfence();
            atomicExch(&g_bar_sense, s);
        } else {
            while (atomicAdd(&g_bar_sense, 0) != s) __nanosleep(32);
        }
        __threadfence();
    }
    __syncthreads();
}

// ---------------------------------------------------------------------------
// Tiled fp32 GEMM tile: C[row0+m, coff+n] = sum_k A[row0+m,k]*B[n,k]
// 64x64 tile, BK=16, first 256 threads active, 4x4 microtile, FFMA2,
// A duplicated in smem. Smem passed in: As2 [2][16][132], Bs [2][16][68].
// ---------------------------------------------------------------------------
__device__ __forceinline__ void gemm_tile(
    const float* __restrict__ A, const float* __restrict__ B,
    float* __restrict__ C, int K, int ldc, int coff, int row0,
    float* __restrict__ As2, float* __restrict__ Bs)
{
    const int tid = threadIdx.x;
    const bool act = tid < 256;
    const int tx = tid & 15, ty = (tid >> 4) & 15;
    const int ty8 = ty * 8, tx4 = tx * 4;
    const int lr = (tid >> 2) & 63;
    const int lk = (tid & 3) * 4;

    ull acc[4][2];
#pragma unroll
    for (int i = 0; i < 4; i++) { acc[i][0] = 0ull; acc[i][1] = 0ull; }

    const float* ap = &A[(size_t)(row0 + lr) * K + lk];
    const float* bp = &B[(size_t)lr * K + lk];

    if (act) {
        float4 av = *(const float4*)ap;
        float4 bv = *(const float4*)bp;
        *(float2*)&As2[(lk + 0) * 132 + 2 * lr] = make_float2(av.x, av.x);
        *(float2*)&As2[(lk + 1) * 132 + 2 * lr] = make_float2(av.y, av.y);
        *(float2*)&As2[(lk + 2) * 132 + 2 * lr] = make_float2(av.z, av.z);
        *(float2*)&As2[(lk + 3) * 132 + 2 * lr] = make_float2(av.w, av.w);
        Bs[(lk + 0) * 68 + lr] = bv.x; Bs[(lk + 1) * 68 + lr] = bv.y;
        Bs[(lk + 2) * 68 + lr] = bv.z; Bs[(lk + 3) * 68 + lr] = bv.w;
    }
    __syncthreads();

    int buf = 0;
    for (int k0 = 0; k0 < K; k0 += 16) {
        float4 av2, bv2;
        const bool more = (k0 + 16 < K);
        if (act && more) {
            av2 = *(const float4*)(ap + k0 + 16);
            bv2 = *(const float4*)(bp + k0 + 16);
        }
        if (act) {
            float* Ab = As2 + buf * 2112;
            float* Bb = Bs + buf * 1088;
#pragma unroll
            for (int kk = 0; kk < 16; kk++) {
                ulonglong2 aP = *(const ulonglong2*)&Ab[kk * 132 + ty8];
                ulonglong2 aQ = *(const ulonglong2*)&Ab[kk * 132 + ty8 + 4];
                ulonglong2 b  = *(const ulonglong2*)&Bb[kk * 68 + tx4];
                fma2(acc[0][0], aP.x, b.x); fma2(acc[0][1], aP.x, b.y);
                fma2(acc[1][0], aP.y, b.x); fma2(acc[1][1], aP.y, b.y);
                fma2(acc[2][0], aQ.x, b.x); fma2(acc[2][1], aQ.x, b.y);
                fma2(acc[3][0], aQ.y, b.x); fma2(acc[3][1], aQ.y, b.y);
            }
        }
        if (act && more) {
            const int nb = buf ^ 1;
            float* Ab = As2 + nb * 2112;
            float* Bb = Bs + nb * 1088;
            *(float2*)&Ab[(lk + 0) * 132 + 2 * lr] = make_float2(av2.x, av2.x);
            *(float2*)&Ab[(lk + 1) * 132 + 2 * lr] = make_float2(av2.y, av2.y);
            *(float2*)&Ab[(lk + 2) * 132 + 2 * lr] = make_float2(av2.z, av2.z);
            *(float2*)&Ab[(lk + 3) * 132 + 2 * lr] = make_float2(av2.w, av2.w);
            Bb[(lk + 0) * 68 + lr] = bv2.x; Bb[(lk + 1) * 68 + lr] = bv2.y;
            Bb[(lk + 2) * 68 + lr] = bv2.z; Bb[(lk + 3) * 68 + lr] = bv2.w;
        }
        __syncthreads();
        buf ^= 1;
    }

    if (act) {
#pragma unroll
        for (int i = 0; i < 4; i++) {
            float2 p0 = unpk(acc[i][0]);
            float2 p1 = unpk(acc[i][1]);
            float4 o; o.x = p0.x; o.y = p0.y; o.z = p1.x; o.w = p1.y;
            *(float4*)&C[(size_t)(row0 + ty * 4 + i) * ldc + coff + tx4] = o;
        }
    }
}

// ---------------------------------------------------------------------------
// The single persistent kernel: proj -> phi -> chunk_kv -> prefix -> attn -> out
// ---------------------------------------------------------------------------
__global__ void __launch_bounds__(NTHR) fused_kernel(
    const float* __restrict__ hs, const float* __restrict__ Wq,
    const float* __restrict__ Wk, const float* __restrict__ Wv,
    const float* __restrict__ Wo, float* __restrict__ out)
{
    extern __shared__ char smraw[];
    float* smf = (float*)smraw;
    __shared__ int sense_sh;
    const int tid = threadIdx.x;
    const int bid = blockIdx.x;
    if (tid == 0) sense_sh = atomicAdd(&g_bar_sense, 0);

    // ======== Phase 1: fused q|k|v projection (144 tile units) ========
    {
        float* As2 = smf;            // [2][16][132]
        float* Bs  = smf + 4224;     // [2][16][68]
        for (int u = bid; u < 144; u += GRID_P) {
            const int cb = u >> 3, bx = u & 7;
            const float* B; int coff;
            if (cb < 3)      { B = Wq + (size_t)cb * 64 * DM;        coff = cb * 64; }
            else if (cb < 6) { B = Wk + (size_t)(cb - 3) * 64 * DM;  coff = 192 + (cb - 3) * 64; }
            else             { B = Wv + (size_t)(cb - 6) * 64 * DM;  coff = 384 + (cb - 6) * 64; }
            gemm_tile(hs, B, g_P, DM, PROJ_N, coff, bx * 64, As2, Bs);
            __syncthreads();
        }
    }
    grid_sync(&sense_sh);

    // ======== Phase 2: Taylor feature map (512 position units) ========
    {
        float* sx = smf;             // 384 floats
        const int d = tid;           // 0..287
        int mode, ii = 0, jj = 0;
        if (d == 0) mode = 0;
        else if (d <= 16) { mode = 1; ii = d - 1; }
        else if (d < DREAL) { mode = 2; const int e = d - 17; ii = e >> 4; jj = e & 15; }
        else mode = 3;

        for (int l = bid; l < LSEQ; l += GRID_P) {
            for (int i = tid; i < 384; i += NTHR) sx[i] = g_P[(size_t)l * PROJ_N + i];
            __syncthreads();
            const size_t base = (size_t)l * DP + d;
#pragma unroll
            for (int h = 0; h < NH; h++) {
                const float* xq = &sx[h * FD];
                const float* xk = &sx[192 + h * FD];
                float vq, vk;
                if (mode == 0)      { vq = 1.f; vk = 1.f; }
                else if (mode == 1) { vq = xq[ii] * 0.5f; vk = xk[ii] * 0.5f; }
                else if (mode == 2) { vq = xq[ii] * xq[jj] * PHI_S; vk = xk[ii] * xk[jj] * PHI_S; }
                else                { vq = 0.f; vk = 0.f; }
                g_phiQ[(size_t)h * LSEQ * DP + base] = vq;
                g_phiK[(size_t)h * LSEQ * DP + base] = vk;
            }
            __syncthreads();
        }
    }
    grid_sync(&sense_sh);

    // ======== Phase 3: per-chunk KV sums (96 units) ========
    {
        float* sV = smf;             // [64][68]
        const int d = tid;           // 0..287
        for (int u = bid; u < 96; u += GRID_P) {
            const int c = u & 7, h = u >> 3;
            for (int idx = tid; idx < CT * HD; idx += NTHR) {
                const int t = idx >> 6, j = idx & 63;
                sV[t * 68 + j] = g_P[(size_t)(c * CT + t) * PROJ_N + 384 + h * HD + j];
            }
            __syncthreads();

            ull acc[32];
#pragma unroll
            for (int i = 0; i < 32; i++) acc[i] = 0ull;
            float zs = 0.f;

            const float* pk = &g_phiK[(size_t)(h * LSEQ + c * CT) * DP + d];
#pragma unroll 2
            for (int t = 0; t < CT; t++) {
                const float kd = pk[(size_t)t * DP];
                zs += kd;
                const ull kdp = dup2(kd);
                const float* vr = &sV[t * 68];
#pragma unroll
                for (int j = 0; j < 16; j++) {
                    ulonglong2 v = *(const ulonglong2*)&vr[j * 4];
                    fma2(acc[2 * j + 0], kdp, v.x);
                    fma2(acc[2 * j + 1], kdp, v.y);
                }
            }
            float* outp = &g_S[((size_t)(h * CH + c) * DP + d) * HD];
#pragma unroll
            for (int j = 0; j < 16; j++) {
                float2 p0 = unpk(acc[2 * j + 0]);
                float2 p1 = unpk(acc[2 * j + 1]);
                float4 o; o.x = p0.x; o.y = p0.y; o.z = p1.x; o.w = p1.y;
                *(float4*)&outp[j * 4] = o;
            }
            g_Z[(size_t)(h * CH + c) * DP + d] = zs;
            __syncthreads();
        }
    }
    grid_sync(&sense_sh);

    // ======== Phase 4: exclusive prefix over chunks (lane-parallel) ========
    {
        const int total = NSLANE + NZLANE;
        for (int i = bid * NTHR + tid; i < total; i += GRID_P * NTHR) {
            if (i < NSLANE) {
                const int h = i / (DP * HD);
                const int r = i - h * (DP * HD);
                const size_t base = (size_t)h * CH * DP * HD + r;
                float v[CH];
#pragma unroll
                for (int c = 0; c < CH; c++) v[c] = g_S[base + (size_t)c * DP * HD];
                float carry = 0.f;
#pragma unroll
                for (int c = 0; c < CH; c++) {
                    g_S[base + (size_t)c * DP * HD] = carry;
                    carry += v[c];
                }
            } else {
                const int z = i - NSLANE;
                const int h = z / DP;
                const int d = z - h * DP;
                const size_t base = (size_t)h * CH * DP + d;
                float v[CH];
#pragma unroll
                for (int c = 0; c < CH; c++) v[c] = g_Z[base + (size_t)c * DP];
                float carry = 0.f;
#pragma unroll
                for (int c = 0; c < CH; c++) {
                    g_Z[base + (size_t)c * DP] = carry;
                    carry += v[c];
                }
            }
        }
    }
    grid_sync(&sense_sh);

    // ======== Phase 5: per-chunk attention output (96 units) ========
    {
        // smem overlay (floats): sAd[64][132] @0, sV[64][68] @8448,
        // sQt2[16][132] @12800, sKt[16][68] @14912, sS[16][68] @16000,
        // sZ[16] @17088, sDen[64] @17104
        float* sAd = smf;
        float* sV  = smf + 8448;
        float* sQt2 = smf + 12800;
        float* sKt = smf + 14912;
        float* sS  = smf + 16000;
        float* sZ  = smf + 17088;
        float* sDen = smf + 17104;

        const bool act = tid < 256;
        const int tx = tid & 15, ty = (tid >> 4) & 15;
        const int ty4 = ty * 4, tx4 = tx * 4, ty8 = ty * 8;
        const int lr = (tid >> 2) & 63;
        const int lc = (tid & 3) * 4;

        for (int u = bid; u < 96; u += GRID_P) {
            const int c = u & 7, h = u >> 3;

            if (act)
                for (int idx = tid; idx < CT * HD; idx += 256) {
                    const int t = idx >> 6, j = idx & 63;
                    sV[t * 68 + j] = g_P[(size_t)(c * CT + t) * PROJ_N + 384 + h * HD + j];
                }

            const float* phq = &g_phiQ[(size_t)(h * LSEQ + c * CT) * DP];
            const float* phk = &g_phiK[(size_t)(h * LSEQ + c * CT) * DP];
            const float* Sp = &g_S[(size_t)(h * CH + c) * DP * HD];
            const float* Zp = &g_Z[(size_t)(h * CH + c) * DP];

            ull accA[4][2], accY[4][2];
#pragma unroll
            for (int i = 0; i < 4; i++) {
                accA[i][0] = 0ull; accA[i][1] = 0ull;
                accY[i][0] = 0ull; accY[i][1] = 0ull;
            }
            float den0 = 0.f, den1 = 0.f, den2 = 0.f, den3 = 0.f;

            float4 qv, kv, sv; float zv = 0.f;
            if (act) {
                qv = *(const float4*)&phq[(size_t)lr * DP + lc];
                kv = *(const float4*)&phk[(size_t)lr * DP + lc];
                sv = *(const float4*)&Sp[(size_t)ty * HD + tx4];
                if (tid < 16) zv = Zp[tid];
            }

            for (int d0 = 0; d0 < DP; d0 += 16) {
                if (act) {
                    *(float2*)&sQt2[(lc + 0) * 132 + 2 * lr] = make_float2(qv.x, qv.x);
                    *(float2*)&sQt2[(lc + 1) * 132 + 2 * lr] = make_float2(qv.y, qv.y);
                    *(float2*)&sQt2[(lc + 2) * 132 + 2 * lr] = make_float2(qv.z, qv.z);
                    *(float2*)&sQt2[(lc + 3) * 132 + 2 * lr] = make_float2(qv.w, qv.w);
                    sKt[(lc + 0) * 68 + lr] = kv.x; sKt[(lc + 1) * 68 + lr] = kv.y;
                    sKt[(lc + 2) * 68 + lr] = kv.z; sKt[(lc + 3) * 68 + lr] = kv.w;
                    *(float4*)&sS[ty * 68 + tx4] = sv;
                    if (tid < 16) sZ[tid] = zv;
                }
                __syncthreads();

                const int dn = d0 + 16;
                if (act && dn < DP) {
                    qv = *(const float4*)&phq[(size_t)lr * DP + dn + lc];
                    kv = *(const float4*)&phk[(size_t)lr * DP + dn + lc];
                    sv = *(const float4*)&Sp[(size_t)(dn + ty) * HD + tx4];
                    if (tid < 16) zv = Zp[dn + tid];
                }

                if (act) {
#pragma unroll
                    for (int dd = 0; dd < 16; dd++) {
                        ulonglong2 aP = *(const ulonglong2*)&sQt2[dd * 132 + ty8];
                        ulonglong2 aQ = *(const ulonglong2*)&sQt2[dd * 132 + ty8 + 4];
                        ulonglong2 kp = *(const ulonglong2*)&sKt[dd * 68 + tx4];
                        ulonglong2 sp = *(const ulonglong2*)&sS[dd * 68 + tx4];
                        fma2(accA[0][0], aP.x, kp.x); fma2(accA[0][1], aP.x, kp.y);
                        fma2(accA[1][0], aP.y, kp.x); fma2(accA[1][1], aP.y, kp.y);
                        fma2(accA[2][0], aQ.x, kp.x); fma2(accA[2][1], aQ.x, kp.y);
                        fma2(accA[3][0], aQ.y, kp.x); fma2(accA[3][1], aQ.y, kp.y);
                        fma2(accY[0][0], aP.x, sp.x); fma2(accY[0][1], aP.x, sp.y);
                        fma2(accY[1][0], aP.y, sp.x); fma2(accY[1][1], aP.y, sp.y);
                        fma2(accY[2][0], aQ.x, sp.x); fma2(accY[2][1], aQ.x, sp.y);
                        fma2(accY[3][0], aQ.y, sp.x); fma2(accY[3][1], aQ.y, sp.y);
                        if (tx == 0) {
                            const float z = sZ[dd];
                            den0 += unpk(aP.x).x * z; den1 += unpk(aP.y).x * z;
                            den2 += unpk(aQ.x).x * z; den3 += unpk(aQ.y).x * z;
                        }
                    }
                }
                __syncthreads();
            }

            if (act) {
#pragma unroll
                for (int i = 0; i < 4; i++) {
                    float2 p0 = unpk(accA[i][0]);
                    float2 p1 = unpk(accA[i][1]);
                    const int t = ty4 + i;
                    float m0 = (tx4 + 0 <= t) ? p0.x : 0.f;
                    float m1 = (tx4 + 1 <= t) ? p0.y : 0.f;
                    float m2 = (tx4 + 2 <= t) ? p1.x : 0.f;
                    float m3 = (tx4 + 3 <= t) ? p1.y : 0.f;
                    *(float2*)&sAd[t * 132 + 2 * (tx4 + 0)] = make_float2(m0, m0);
                    *(float2*)&sAd[t * 132 + 2 * (tx4 + 1)] = make_float2(m1, m1);
                    *(float2*)&sAd[t * 132 + 2 * (tx4 + 2)] = make_float2(m2, m2);
                    *(float2*)&sAd[t * 132 + 2 * (tx4 + 3)] = make_float2(m3, m3);
                }
            }
            __syncthreads();

            if (act) {
#pragma unroll 4
                for (int s = 0; s < CT; s++) {
                    ull a0 = *(const ull*)&sAd[(ty4 + 0) * 132 + 2 * s];
                    ull a1 = *(const ull*)&sAd[(ty4 + 1) * 132 + 2 * s];
                    ull a2 = *(const ull*)&sAd[(ty4 + 2) * 132 + 2 * s];
                    ull a3 = *(const ull*)&sAd[(ty4 + 3) * 132 + 2 * s];
                    ulonglong2 v = *(const ulonglong2*)&sV[s * 68 + tx4];
                    fma2(accY[0][0], a0, v.x); fma2(accY[0][1], a0, v.y);
                    fma2(accY[1][0], a1, v.x); fma2(accY[1][1], a1, v.y);
                    fma2(accY[2][0], a2, v.x); fma2(accY[2][1], a2, v.y);
                    fma2(accY[3][0], a3, v.x); fma2(accY[3][1], a3, v.y);
                }
                if (tx == 0) {
                    float r0 = den0 + EPSV, r1 = den1 + EPSV, r2 = den2 + EPSV, r3 = den3 + EPSV;
#pragma unroll 8
                    for (int s = 0; s < CT; s++) {
                        r0 += sAd[(ty4 + 0) * 132 + 2 * s];
                        r1 += sAd[(ty4 + 1) * 132 + 2 * s];
                        r2 += sAd[(ty4 + 2) * 132 + 2 * s];
                        r3 += sAd[(ty4 + 3) * 132 + 2 * s];
                    }
                    sDen[ty4 + 0] = r0; sDen[ty4 + 1] = r1;
                    sDen[ty4 + 2] = r2; sDen[ty4 + 3] = r3;
                }
            }
            __syncthreads();

            if (act) {
                float* yo = &g_Y[(size_t)(c * CT) * DM + h * HD + tx4];
#pragma unroll
                for (int i = 0; i < 4; i++) {
                    const float inv = 1.f / sDen[ty4 + i];
                    float2 p0 = unpk(accY[i][0]);
                    float2 p1 = unpk(accY[i][1]);
                    float4 o;
                    o.x = p0.x * inv; o.y = p0.y * inv; o.z = p1.x * inv; o.w = p1.y * inv;
                    *(float4*)&yo[(size_t)(ty4 + i) * DM] = o;
                }
            }
            __syncthreads();
        }
    }
    grid_sync(&sense_sh);

    // ======== Phase 6: output projection (96 units) ========
    {
        float* As2 = smf;
        float* Bs  = smf + 4224;
        for (int u = bid; u < 96; u += GRID_P) {
            const int by = u >> 3, bx = u & 7;
            gemm_tile(g_Y, Wo + (size_t)by * 64 * DM, out, DM, DM,
                      by * 64, bx * 64, As2, Bs);
            __syncthreads();
        }
    }
}

// ---------------------------------------------------------------------------
extern "C" void kernel_launch(void* const* d_in, const int* in_sizes, int n_in,
                              void* d_out, int out_size)
{
    const float* hs = (const float*)d_in[0];
    const float* Wq = (const float*)d_in[1];
    const float* Wk = (const float*)d_in[2];
    const float* Wv = (const float*)d_in[3];
    const float* Wo = (const float*)d_in[4];
    float* out = (float*)d_out;

    cudaFuncSetAttribute(fused_kernel,
                         cudaFuncAttributeMaxDynamicSharedMemorySize, 69632);
    fused_kernel<<<GRID_P, NTHR, 69632>>>(hs, Wq, Wk, Wv, Wo, out);
}